// round 2
// baseline (speedup 1.0000x reference)
#include <cuda_runtime.h>
#include <math.h>

#define AD 1024
#define BD 16384
#define DD 768
#define TEMPC 100.0f
#define EPSC 1e-8f
#define NONDIFF 30
#define DIFFST 10

// ---- device scratch (allocation-free: __device__ globals) ----
__device__ float g_anorm[AD * DD];        // 3 MB
__device__ float g_X[AD * AD];            // 4 MB
__device__ float g_rsx[AD];
__device__ float g_q[AD * BD];            // 64 MB
__device__ float g_c[AD * BD];            // 64 MB
__device__ float g_grad[AD * BD];         // 64 MB
__device__ float g_sm[AD * BD];           // 64 MB
__device__ float g_xsm[AD * BD];          // 64 MB
__device__ float g_ynorm[BD];
__device__ float g_invyn[BD];
__device__ int   g_amin[AD];
__device__ float g_num[BD];
__device__ float g_denpart[BD / 32];      // 512 partials

// =====================================================================
// small init kernels
// =====================================================================
__global__ void ynorm_kernel(const float* __restrict__ y) {
    int w = (blockIdx.x * blockDim.x + threadIdx.x) >> 5;
    int lane = threadIdx.x & 31;
    if (w >= BD) return;
    const float* row = y + (size_t)w * DD;
    float s = 0.f;
    for (int d = lane; d < DD; d += 32) s += fabsf(row[d]);
#pragma unroll
    for (int o = 16; o; o >>= 1) s += __shfl_xor_sync(0xffffffffu, s, o);
    if (!lane) { g_ynorm[w] = s; g_invyn[w] = 1.0f / s; }
}

__global__ void anorm_kernel(const float* __restrict__ atoms) {
    int r = blockIdx.x;
    const float* row = atoms + (size_t)r * DD;
    __shared__ float red[256];
    float s = 0.f;
    for (int d = threadIdx.x; d < DD; d += 256) s += fabsf(row[d]);
    red[threadIdx.x] = s;
    __syncthreads();
    for (int o = 128; o; o >>= 1) {
        if (threadIdx.x < o) red[threadIdx.x] += red[threadIdx.x + o];
        __syncthreads();
    }
    float nrm = red[0];
    for (int d = threadIdx.x; d < DD; d += 256)
        g_anorm[r * DD + d] = row[d] / nrm;
}

__global__ void rowsumX_kernel() {
    int w = (blockIdx.x * blockDim.x + threadIdx.x) >> 5;
    int lane = threadIdx.x & 31;
    if (w >= AD) return;
    float s = 0.f;
    for (int k = lane; k < AD; k += 32) s += g_X[w * AD + k];
#pragma unroll
    for (int o = 16; o; o >>= 1) s += __shfl_xor_sync(0xffffffffu, s, o);
    if (!lane) g_rsx[w] = s;
}

// c = 1/A ; grad = rowsum(X)/A - q  (since X @ (1/A) = rowsum/A)
__global__ void init_kernel() {
    size_t i4 = ((size_t)blockIdx.x * 256 + threadIdx.x) * 4;
    int a = (int)(i4 / BD);
    float rs = g_rsx[a] * (1.0f / AD);
    float4 q4 = *reinterpret_cast<const float4*>(g_q + i4);
    float4 g;
    g.x = rs - q4.x; g.y = rs - q4.y; g.z = rs - q4.z; g.w = rs - q4.w;
    *reinterpret_cast<float4*>(g_grad + i4) = g;
    float4 cc = make_float4(1.0f / AD, 1.0f / AD, 1.0f / AD, 1.0f / AD);
    *reinterpret_cast<float4*>(g_c + i4) = cc;
}

// =====================================================================
// generic fp32 SIMT GEMM: C[m,n] = sum_k Aop(m,k) * Bop(k,n)
// AKM: A stored [K,M] (index k*lda+m) else [M,K] (m*lda+k)
// BKM: B stored [K,N] (index k*ldb+n) else [N,K] (n*ldb+k)
// SCALE: 0 none, 1 C *= scale[n], 2 C *= scale[m]
// dims must be multiples of 128 (M,N) and 16 (K) — true for all uses.
// =====================================================================
template <bool AKM, bool BKM, int SCALE>
__global__ void __launch_bounds__(256) gemm_kernel(
    const float* __restrict__ A, const float* __restrict__ B, float* __restrict__ C,
    int M, int N, int K, int lda, int ldb, int ldc, const float* __restrict__ scale)
{
    __shared__ float As[16][132];
    __shared__ float Bs[16][132];
    const int tid = threadIdx.x;
    const int tx = tid & 15, ty = tid >> 4;
    const int m0 = blockIdx.y * 128, n0 = blockIdx.x * 128;
    float acc[8][8];
#pragma unroll
    for (int i = 0; i < 8; i++)
#pragma unroll
        for (int j = 0; j < 8; j++) acc[i][j] = 0.f;

    for (int k0 = 0; k0 < K; k0 += 16) {
#pragma unroll
        for (int i = 0; i < 2; i++) {
            int lin = tid + i * 256;
            if (AKM) {
                int kk = lin >> 5, mm = (lin & 31) << 2;
                float4 v = *reinterpret_cast<const float4*>(A + (size_t)(k0 + kk) * lda + (m0 + mm));
                *reinterpret_cast<float4*>(&As[kk][mm]) = v;
            } else {
                int mm = lin >> 2, kk = (lin & 3) << 2;
                float4 v = *reinterpret_cast<const float4*>(A + (size_t)(m0 + mm) * lda + (k0 + kk));
                As[kk + 0][mm] = v.x; As[kk + 1][mm] = v.y;
                As[kk + 2][mm] = v.z; As[kk + 3][mm] = v.w;
            }
        }
#pragma unroll
        for (int i = 0; i < 2; i++) {
            int lin = tid + i * 256;
            if (BKM) {
                int kk = lin >> 5, nn = (lin & 31) << 2;
                float4 v = *reinterpret_cast<const float4*>(B + (size_t)(k0 + kk) * ldb + (n0 + nn));
                *reinterpret_cast<float4*>(&Bs[kk][nn]) = v;
            } else {
                int nn = lin >> 2, kk = (lin & 3) << 2;
                float4 v = *reinterpret_cast<const float4*>(B + (size_t)(n0 + nn) * ldb + (k0 + kk));
                Bs[kk + 0][nn] = v.x; Bs[kk + 1][nn] = v.y;
                Bs[kk + 2][nn] = v.z; Bs[kk + 3][nn] = v.w;
            }
        }
        __syncthreads();
#pragma unroll
        for (int k = 0; k < 16; k++) {
            float af[8], bf[8];
            *reinterpret_cast<float4*>(&af[0]) = *reinterpret_cast<float4*>(&As[k][ty * 8]);
            *reinterpret_cast<float4*>(&af[4]) = *reinterpret_cast<float4*>(&As[k][ty * 8 + 4]);
            *reinterpret_cast<float4*>(&bf[0]) = *reinterpret_cast<float4*>(&Bs[k][tx * 8]);
            *reinterpret_cast<float4*>(&bf[4]) = *reinterpret_cast<float4*>(&Bs[k][tx * 8 + 4]);
#pragma unroll
            for (int i = 0; i < 8; i++)
#pragma unroll
                for (int j = 0; j < 8; j++) acc[i][j] += af[i] * bf[j];
        }
        __syncthreads();
    }
#pragma unroll
    for (int i = 0; i < 8; i++) {
        int m = m0 + ty * 8 + i;
        float rowf = (SCALE == 2) ? scale[m] : 1.f;
#pragma unroll
        for (int j = 0; j < 8; j++) {
            float f = (SCALE == 1) ? scale[n0 + tx * 8 + j] : rowf;
            C[(size_t)m * ldc + n0 + tx * 8 + j] = acc[i][j] * f;
        }
    }
}

// =====================================================================
// argmin over batch per atom row (first-occurrence min, JAX semantics)
// =====================================================================
__global__ void argmin_kernel() {
    int a = blockIdx.x;
    const float* row = g_grad + (size_t)a * BD;
    float bv = INFINITY; int bi = 0;
    for (int j = threadIdx.x; j < BD; j += 256) {
        float v = row[j];
        if (v < bv) { bv = v; bi = j; }
    }
    __shared__ float sv[256];
    __shared__ int   si[256];
    sv[threadIdx.x] = bv; si[threadIdx.x] = bi;
    __syncthreads();
    for (int o = 128; o; o >>= 1) {
        if (threadIdx.x < o) {
            float v2 = sv[threadIdx.x + o]; int i2 = si[threadIdx.x + o];
            if (v2 < sv[threadIdx.x] ||
                (v2 == sv[threadIdx.x] && i2 < si[threadIdx.x])) {
                sv[threadIdx.x] = v2; si[threadIdx.x] = i2;
            }
        }
        __syncthreads();
    }
    if (!threadIdx.x) g_amin[a] = si[0];
}

// deterministic ballot-compacted selection list (ascending atom order)
__device__ __forceinline__ void build_sel_list(
    const int* amin_s, int j0, int* sel_a, int* sel_j, int* nsel_s,
    int tid, int tx)
{
    if (tid < 32) {
        int cnt = 0;
        for (int base = 0; base < AD; base += 32) {
            int a = base + tx;
            int jm = amin_s[a];
            bool mt = (jm >= j0 && jm < j0 + 32);
            unsigned mask = __ballot_sync(0xffffffffu, mt);
            if (mt) {
                int p = cnt + __popc(mask & ((1u << tx) - 1u));
                sel_a[p] = a; sel_j[p] = jm;
            }
            cnt += __popc(mask);
        }
        if (tx == 0) *nsel_s = cnt;
    }
}

// =====================================================================
// nondiff step: column-tile kernels. block = (32 cols, 8 row-threads)
//   d  = am - c ;  Xd = S - grad - q  where S = X @ am (column scatter)
//   num[j] = sum_a d*grad ; denpart = partial of sum d*Xd
// =====================================================================
__global__ void __launch_bounds__(256) nd_reduce_kernel() {
    const int tx = threadIdx.x, ty = threadIdx.y, tid = ty * 32 + tx;
    const int j0 = blockIdx.x * 32, j = j0 + tx;
    __shared__ int amin_s[AD];
    __shared__ int sel_a[AD], sel_j[AD], nsel_s;
    for (int a = tid; a < AD; a += 256) amin_s[a] = g_amin[a];
    __syncthreads();
    build_sel_list(amin_s, j0, sel_a, sel_j, &nsel_s, tid, tx);
    __syncthreads();
    const int ns = nsel_s;

    float num = 0.f, den = 0.f;
    for (int a = ty; a < AD; a += 8) {
        size_t idx = (size_t)a * BD + j;
        float cc = g_c[idx], gg = g_grad[idx], qq = g_q[idx];
        float S = 0.f;
        for (int e = 0; e < ns; e++)
            if (sel_j[e] == j) S += g_X[a * AD + sel_a[e]];
        float am = (amin_s[a] == j) ? 1.f : 0.f;
        float dd = am - cc;
        num += dd * gg;
        den += dd * (S - gg - qq);
    }
    __shared__ float rn[8][33], rd[8][33], colden[32];
    rn[ty][tx] = num; rd[ty][tx] = den;
    __syncthreads();
    if (ty == 0) {
        float n2 = 0.f, d2 = 0.f;
        for (int t = 0; t < 8; t++) { n2 += rn[t][tx]; d2 += rd[t][tx]; }
        g_num[j] = n2; colden[tx] = d2;
    }
    __syncthreads();
    if (tid == 0) {
        float d3 = 0.f;
        for (int t = 0; t < 32; t++) d3 += colden[t];
        g_denpart[blockIdx.x] = d3;
    }
}

__global__ void __launch_bounds__(256) nd_update_kernel() {
    const int tx = threadIdx.x, ty = threadIdx.y, tid = ty * 32 + tx;
    const int j0 = blockIdx.x * 32, j = j0 + tx;
    __shared__ float red[256];
    __shared__ int amin_s[AD];
    __shared__ int sel_a[AD], sel_j[AD], nsel_s;
    red[tid] = g_denpart[tid] + g_denpart[tid + 256];
    for (int a = tid; a < AD; a += 256) amin_s[a] = g_amin[a];
    __syncthreads();
    for (int o = 128; o; o >>= 1) {
        if (tid < o) red[tid] += red[tid + o];
        __syncthreads();
    }
    build_sel_list(amin_s, j0, sel_a, sel_j, &nsel_s, tid, tx);
    __syncthreads();
    const int ns = nsel_s;
    const float denom = red[0] + EPSC;
    const float lam = fminf(fmaxf(-g_num[j] / denom, 0.f), 1.f);

    for (int a = ty; a < AD; a += 8) {
        size_t idx = (size_t)a * BD + j;
        float cc = g_c[idx], gg = g_grad[idx], qq = g_q[idx];
        float S = 0.f;
        for (int e = 0; e < ns; e++)
            if (sel_j[e] == j) S += g_X[a * AD + sel_a[e]];
        float am = (amin_s[a] == j) ? 1.f : 0.f;
        float dd = am - cc;
        float xd = S - gg - qq;
        g_c[idx]   = cc + lam * dd;
        g_grad[idx] = gg + lam * xd;
    }
}

// =====================================================================
// diff step kernels
// =====================================================================
__global__ void __launch_bounds__(256) softmax_kernel() {
    const int tx = threadIdx.x, ty = threadIdx.y;
    const int j = blockIdx.x * 32 + tx;
    float m = -INFINITY, s = 0.f;
    for (int a = ty; a < AD; a += 8) {
        float v = -TEMPC * g_grad[(size_t)a * BD + j];
        if (v > m) { s = s * expf(m - v) + 1.f; m = v; }
        else        s += expf(v - m);
    }
    __shared__ float mm[8][33], ss[8][33], fm[32], fs[32];
    mm[ty][tx] = m; ss[ty][tx] = s;
    __syncthreads();
    if (ty == 0) {
        float M = mm[0][tx], S = ss[0][tx];
        for (int t = 1; t < 8; t++) {
            float m2 = mm[t][tx], s2 = ss[t][tx];
            float Mn = fmaxf(M, m2);
            S = S * expf(M - Mn) + s2 * expf(m2 - Mn);
            M = Mn;
        }
        fm[tx] = M; fs[tx] = S;
    }
    __syncthreads();
    const float M = fm[tx];
    const float invS = 1.0f / fs[tx];
    for (int a = ty; a < AD; a += 8) {
        size_t idx = (size_t)a * BD + j;
        float v = -TEMPC * g_grad[idx];
        g_sm[idx] = expf(v - M) * invS;
    }
}

__global__ void __launch_bounds__(256) d_reduce_kernel() {
    const int tx = threadIdx.x, ty = threadIdx.y, tid = ty * 32 + tx;
    const int j = blockIdx.x * 32 + tx;
    float num = 0.f, den = 0.f;
    for (int a = ty; a < AD; a += 8) {
        size_t idx = (size_t)a * BD + j;
        float dd = g_sm[idx] - g_c[idx];
        float xd = g_xsm[idx] - g_grad[idx] - g_q[idx];
        num += dd * g_grad[idx];
        den += dd * xd;
    }
    __shared__ float rn[8][33], rd[8][33], colden[32];
    rn[ty][tx] = num; rd[ty][tx] = den;
    __syncthreads();
    if (ty == 0) {
        float n2 = 0.f, d2 = 0.f;
        for (int t = 0; t < 8; t++) { n2 += rn[t][tx]; d2 += rd[t][tx]; }
        g_num[j] = n2; colden[tx] = d2;
    }
    __syncthreads();
    if (tid == 0) {
        float d3 = 0.f;
        for (int t = 0; t < 32; t++) d3 += colden[t];
        g_denpart[blockIdx.x] = d3;
    }
}

__global__ void __launch_bounds__(256) d_update_kernel() {
    const int tx = threadIdx.x, ty = threadIdx.y, tid = ty * 32 + tx;
    const int j = blockIdx.x * 32 + tx;
    __shared__ float red[256];
    red[tid] = g_denpart[tid] + g_denpart[tid + 256];
    __syncthreads();
    for (int o = 128; o; o >>= 1) {
        if (tid < o) red[tid] += red[tid + o];
        __syncthreads();
    }
    const float denom = red[0] + EPSC;
    const float lam = fminf(fmaxf(-g_num[j] / denom, 0.f), 1.f);
    for (int a = ty; a < AD; a += 8) {
        size_t idx = (size_t)a * BD + j;
        float cc = g_c[idx], gg = g_grad[idx];
        float dd = g_sm[idx] - cc;
        float xd = g_xsm[idx] - gg - g_q[idx];
        g_c[idx]   = cc + lam * dd;
        g_grad[idx] = gg + lam * xd;
    }
}

// =====================================================================
// host launcher
// =====================================================================
extern "C" void kernel_launch(void* const* d_in, const int* in_sizes, int n_in,
                              void* d_out, int out_size)
{
    const float* y     = (const float*)d_in[0];   // [16384, 3,16,16]
    const float* atoms = (const float*)d_in[1];   // [1024, 3,16,16]
    float* out = (float*)d_out;                   // [16384, 3,16,16]

    float *p_anorm, *p_X, *p_q, *p_sm, *p_xsm, *p_c, *p_invyn, *p_ynorm;
    cudaGetSymbolAddress((void**)&p_anorm, g_anorm);
    cudaGetSymbolAddress((void**)&p_X,     g_X);
    cudaGetSymbolAddress((void**)&p_q,     g_q);
    cudaGetSymbolAddress((void**)&p_sm,    g_sm);
    cudaGetSymbolAddress((void**)&p_xsm,   g_xsm);
    cudaGetSymbolAddress((void**)&p_c,     g_c);
    cudaGetSymbolAddress((void**)&p_invyn, g_invyn);
    cudaGetSymbolAddress((void**)&p_ynorm, g_ynorm);

    ynorm_kernel<<<BD / 8, 256>>>(y);
    anorm_kernel<<<AD, 256>>>(atoms);

    // X = an @ an^T   (NT, M=N=1024, K=768)
    gemm_kernel<false, false, 0><<<dim3(AD / 128, AD / 128), 256>>>(
        p_anorm, p_anorm, p_X, AD, AD, DD, DD, DD, AD, nullptr);
    rowsumX_kernel<<<AD / 8, 256>>>();

    // q = an @ (y/|y|)^T  (NT, M=1024, N=16384, K=768, col-scale 1/|y|)
    gemm_kernel<false, false, 1><<<dim3(BD / 128, AD / 128), 256>>>(
        p_anorm, y, p_q, AD, BD, DD, DD, DD, BD, p_invyn);

    init_kernel<<<(AD * BD) / 1024, 256>>>();

    for (int s = 0; s < NONDIFF; s++) {
        argmin_kernel<<<AD, 256>>>();
        nd_reduce_kernel<<<BD / 32, dim3(32, 8)>>>();
        nd_update_kernel<<<BD / 32, dim3(32, 8)>>>();
    }

    for (int s = 0; s < DIFFST; s++) {
        softmax_kernel<<<BD / 32, dim3(32, 8)>>>();
        // xsm = X @ sm  (NN, M=1024, N=16384, K=1024)
        gemm_kernel<false, true, 0><<<dim3(BD / 128, AD / 128), 256>>>(
            p_X, p_sm, p_xsm, AD, BD, AD, AD, BD, BD, nullptr);
        d_reduce_kernel<<<BD / 32, dim3(32, 8)>>>();
        d_update_kernel<<<BD / 32, dim3(32, 8)>>>();
    }

    // recon = (c^T @ an) * |y|   (TN: A=c as [K=1024, M=16384], B=an [K,768])
    gemm_kernel<true, true, 2><<<dim3(DD / 128, BD / 128), 256>>>(
        p_c, p_anorm, out, BD, DD, AD, BD, DD, DD, p_ynorm);
}